// round 7
// baseline (speedup 1.0000x reference)
#include <cuda_runtime.h>
#include <cuda_fp16.h>
#include <cstdint>

#define Bn 32
#define Gn 512
#define Dn 128
#define Hn 4
#define NORMF 0.17677669529663687f   // 1/sqrt(32)

// Scratch (device globals — no allocation allowed)
__device__ float g_M[4][Bn][Hn][Dn];        // [map: p1,p2,d1,d2][b][h][d]
__device__ uint32_t g_Ah2 [Bn * Gn * 16];   // fc1 i-side partial, half2, perm-k
__device__ uint32_t g_Bvh2[Bn * Gn * 16];   // fc1 j-side partial + b1, half2, perm-k

__constant__ float cFC1W[16][32];
__constant__ float cFC1B[32];
__constant__ float cB2[32];
__constant__ float cW3[32];
__constant__ float cB3[1];

// k-permutation for m16n8k16 A fragments: half2 slot m = 8c + 2q' + s holds
// original cols (k0, k0+1) with k0 = 16c + 2q' + 8s. Thread q then reads the
// uint2 at slot 2q (+8 per chunk) to get cols {2q,2q+1,2q+8,2q+9}.

// -------------------------------------------------------------------------
// prep1: per batch b: Q = q @ Wq (H,K), fold M[b,h,d] = NORM * Q·Wk[h,d,:]
// -------------------------------------------------------------------------
__global__ void __launch_bounds__(512) prep1(const float* __restrict__ h,
                      const int* __restrict__ pp,
                      const int* __restrict__ pd,
                      const float* __restrict__ Wq1,
                      const float* __restrict__ Wk1,
                      const float* __restrict__ Wq2,
                      const float* __restrict__ Wk2) {
    int b = blockIdx.x;
    int t = threadIdx.x;
    __shared__ float shp[Dn], shd[Dn];
    __shared__ float sQp[4][4][128];
    __shared__ float sQ[4][Hn][32];

    int ip = pp[b], id = pd[b];
    if (t < Dn)            shp[t]       = h[(b * Gn + ip) * Dn + t];
    else if (t < 2 * Dn)   shd[t - Dn]  = h[(b * Gn + id) * Dn + (t - Dn)];
    __syncthreads();

    {
        int hk = t & 127;
        int q  = t >> 7;
        int hh = hk >> 5, k = hk & 31;
        float q_p1 = 0.f, q_p2 = 0.f, q_d1 = 0.f, q_d2 = 0.f;
        #pragma unroll 16
        for (int dd = 0; dd < 32; dd++) {
            int d = q * 32 + dd;
            float w1 = Wq1[(hh * Dn + d) * 32 + k];
            float w2 = Wq2[(hh * Dn + d) * 32 + k];
            float xp = shp[d], xd = shd[d];
            q_p1 = fmaf(xp, w1, q_p1);
            q_p2 = fmaf(xp, w2, q_p2);
            q_d1 = fmaf(xd, w1, q_d1);
            q_d2 = fmaf(xd, w2, q_d2);
        }
        sQp[q][0][hk] = q_p1;
        sQp[q][1][hk] = q_p2;
        sQp[q][2][hk] = q_d1;
        sQp[q][3][hk] = q_d2;
    }
    __syncthreads();
    {
        int m = t >> 7, hk = t & 127;
        float s = sQp[0][m][hk] + sQp[1][m][hk] + sQp[2][m][hk] + sQp[3][m][hk];
        sQ[m][hk >> 5][hk & 31] = s;
    }
    __syncthreads();

    {
        int hh = t >> 7, d = t & 127;
        const float4* wk1r = (const float4*)&Wk1[(hh * Dn + d) * 32];
        const float4* wk2r = (const float4*)&Wk2[(hh * Dn + d) * 32];
        float m1 = 0.f, m2 = 0.f, m3 = 0.f, m4 = 0.f;
        #pragma unroll
        for (int i4 = 0; i4 < 8; i4++) {
            float4 a = __ldg(wk1r + i4);
            float4 c = __ldg(wk2r + i4);
            int k0 = i4 * 4;
            m1 = fmaf(sQ[0][hh][k0+0], a.x, m1); m1 = fmaf(sQ[0][hh][k0+1], a.y, m1);
            m1 = fmaf(sQ[0][hh][k0+2], a.z, m1); m1 = fmaf(sQ[0][hh][k0+3], a.w, m1);
            m2 = fmaf(sQ[1][hh][k0+0], c.x, m2); m2 = fmaf(sQ[1][hh][k0+1], c.y, m2);
            m2 = fmaf(sQ[1][hh][k0+2], c.z, m2); m2 = fmaf(sQ[1][hh][k0+3], c.w, m2);
            m3 = fmaf(sQ[2][hh][k0+0], a.x, m3); m3 = fmaf(sQ[2][hh][k0+1], a.y, m3);
            m3 = fmaf(sQ[2][hh][k0+2], a.z, m3); m3 = fmaf(sQ[2][hh][k0+3], a.w, m3);
            m4 = fmaf(sQ[3][hh][k0+0], c.x, m4); m4 = fmaf(sQ[3][hh][k0+1], c.y, m4);
            m4 = fmaf(sQ[3][hh][k0+2], c.z, m4); m4 = fmaf(sQ[3][hh][k0+3], c.w, m4);
        }
        g_M[0][b][hh][d] = m1 * NORMF;
        g_M[1][b][hh][d] = m2 * NORMF;
        g_M[2][b][hh][d] = m3 * NORMF;
        g_M[3][b][hh][d] = m4 * NORMF;
    }
}

// -------------------------------------------------------------------------
// prep2: per (b,g): u/v compat vectors folded through fc1, emitted as
// packed half2 in fragment-permuted k order.
// -------------------------------------------------------------------------
__global__ void __launch_bounds__(128) prep2(const float* __restrict__ h,
                                             const int* __restrict__ rec) {
    int b = blockIdx.y;
    int g = blockIdx.x * 128 + threadIdx.x;
    int t = threadIdx.x;
    __shared__ float sM[4][Hn][Dn];

    for (int idx = t; idx < 4 * Hn * Dn; idx += 128) {
        int w = idx >> 9;
        int r = idx & 511;
        (&sM[0][0][0])[idx] = (&g_M[0][0][0][0])[(w * Bn + b) * (Hn * Dn) + r];
    }
    __syncthreads();

    int nb = rec[b * Gn + g];
    const float4* hrow = (const float4*)(h + (b * Gn + g) * Dn);
    const float4* nrow = (const float4*)(h + (b * Gn + nb) * Dn);

    float u[8], v[8];
    #pragma unroll
    for (int l = 0; l < 8; l++) { u[l] = 0.f; v[l] = 0.f; }

    #pragma unroll 4
    for (int d4 = 0; d4 < Dn / 4; d4++) {
        float4 xv = __ldg(hrow + d4);
        float4 yv = __ldg(nrow + d4);
        float xs[4] = {xv.x, xv.y, xv.z, xv.w};
        float ys[4] = {yv.x, yv.y, yv.z, yv.w};
        #pragma unroll
        for (int r = 0; r < 4; r++) {
            int d = d4 * 4 + r;
            #pragma unroll
            for (int hh = 0; hh < Hn; hh++) {
                u[hh]     = fmaf(xs[r], sM[0][hh][d], u[hh]);
                u[4 + hh] = fmaf(ys[r], sM[1][hh][d], u[4 + hh]);
                v[hh]     = fmaf(xs[r], sM[2][hh][d], v[hh]);
                v[4 + hh] = fmaf(ys[r], sM[3][hh][d], v[4 + hh]);
            }
        }
    }

    float au[32], bu[32];
    #pragma unroll
    for (int k = 0; k < 32; k++) {
        float a = 0.f;
        float bb = cFC1B[k];
        #pragma unroll
        for (int l = 0; l < 8; l++) {
            a  = fmaf(u[l], cFC1W[l][k], a);
            bb = fmaf(v[l], cFC1W[8 + l][k], bb);
        }
        au[k] = a;
        bu[k] = bb;
    }

    uint32_t pa[16], pb[16];
    #pragma unroll
    for (int m = 0; m < 16; m++) {
        int c = m >> 3, rem = m & 7, qq = rem >> 1, s = rem & 1;
        int k0 = 16 * c + 2 * qq + 8 * s;
        __half2 ha = __floats2half2_rn(au[k0], au[k0 + 1]);
        __half2 hb = __floats2half2_rn(bu[k0], bu[k0 + 1]);
        pa[m] = *(uint32_t*)&ha;
        pb[m] = *(uint32_t*)&hb;
    }
    uint4* dA = (uint4*)&g_Ah2 [(b * Gn + g) * 16];
    uint4* dB = (uint4*)&g_Bvh2[(b * Gn + g) * 16];
    #pragma unroll
    for (int c4 = 0; c4 < 4; c4++) {
        dA[c4] = make_uint4(pa[4*c4], pa[4*c4+1], pa[4*c4+2], pa[4*c4+3]);
        dB[c4] = make_uint4(pb[4*c4], pb[4*c4+1], pb[4*c4+2], pb[4*c4+3]);
    }
}

// -------------------------------------------------------------------------
// mlp_mma: fc2 via mma.sync m16n8k16 fp16 (f32 accum). Y1 built with packed
// half2 add/max, no cvt in the hot loop. Bias pre-loaded into accumulators.
// CTA = 256 thr (8 warps) = (b, 8 consecutive i); warp loops 32 j-tiles of 16.
// -------------------------------------------------------------------------
#define BV_STRIDE 20   // uint32 per smem row (80B, 16B-aligned)

__global__ void __launch_bounds__(256, 3) mlp_mma(const float* __restrict__ W2,
                                                  float* __restrict__ out) {
    extern __shared__ uint32_t sBv2[];   // [512][BV_STRIDE]
    const int t = threadIdx.x;
    const int w = t >> 5;
    const int lane = t & 31;
    const int q = lane & 3;          // threadID_in_group
    const int r = lane >> 2;         // groupID
    const int b = blockIdx.y;
    const int i = blockIdx.x * 8 + w;

    // ---- stage Bvh[b] into smem ----
    {
        const uint4* src = (const uint4*)&g_Bvh2[b * Gn * 16];
        for (int idx = t; idx < Gn * 4; idx += 256) {
            int j = idx >> 2, c4 = idx & 3;
            uint4 v = __ldg(src + idx);
            *(uint4*)&sBv2[j * BV_STRIDE + c4 * 4] = v;
        }
    }

    // ---- loop-invariant per-thread data ----
    // A_i fragment sources: uint2 at half2-slot (8c + 2q) = cols {2q,2q+1} (.x)
    // and {2q+8,2q+9} (.y) of chunk c.
    uint2 Ah[2];
    {
        const uint32_t* ar = &g_Ah2[(b * Gn + i) * 16];
        Ah[0] = *(const uint2*)&ar[2 * q];
        Ah[1] = *(const uint2*)&ar[8 + 2 * q];
    }
    // W2 B-fragments (fp16): wb[nbk][c][0] = cols(k) {16c+2q,16c+2q+1} at n=8nbk+r
    uint32_t wb[4][2][2];
    #pragma unroll
    for (int nbk = 0; nbk < 4; nbk++)
        #pragma unroll
        for (int c = 0; c < 2; c++) {
            int n = 8 * nbk + r;
            __half2 w0 = __floats2half2_rn(__ldg(&W2[(16*c + 2*q)     * 32 + n]),
                                           __ldg(&W2[(16*c + 2*q + 1) * 32 + n]));
            __half2 w1 = __floats2half2_rn(__ldg(&W2[(16*c + 2*q + 8) * 32 + n]),
                                           __ldg(&W2[(16*c + 2*q + 9) * 32 + n]));
            wb[nbk][c][0] = *(uint32_t*)&w0;
            wb[nbk][c][1] = *(uint32_t*)&w1;
        }
    float b2v[4][2], w3v[4][2];
    #pragma unroll
    for (int nbk = 0; nbk < 4; nbk++) {
        b2v[nbk][0] = cB2[8 * nbk + 2 * q];
        b2v[nbk][1] = cB2[8 * nbk + 2 * q + 1];
        w3v[nbk][0] = cW3[8 * nbk + 2 * q];
        w3v[nbk][1] = cW3[8 * nbk + 2 * q + 1];
    }
    const float b3 = cB3[0];
    const __half2 hz = __float2half2_rn(0.f);
    __syncthreads();

    float* outrow = out + ((size_t)(b * Gn + i)) * Gn;
    const uint32_t* bvlo = sBv2 + r * BV_STRIDE + 2 * q;        // row j0+r
    const uint32_t* bvhi = sBv2 + (r + 8) * BV_STRIDE + 2 * q;  // row j0+r+8

    for (int jt = 0; jt < 32; jt++) {
        const int j0 = jt * 16;
        const uint32_t* pl = bvlo + j0 * BV_STRIDE;
        const uint32_t* ph = bvhi + j0 * BV_STRIDE;

        // acc init = bias (row-invariant per column)
        float acc[4][4];
        #pragma unroll
        for (int nbk = 0; nbk < 4; nbk++) {
            acc[nbk][0] = b2v[nbk][0]; acc[nbk][1] = b2v[nbk][1];
            acc[nbk][2] = b2v[nbk][0]; acc[nbk][3] = b2v[nbk][1];
        }

        #pragma unroll
        for (int c = 0; c < 2; c++) {
            uint2 rl = *(const uint2*)(pl + 8 * c);
            uint2 rh = *(const uint2*)(ph + 8 * c);
            __half2 av0 = *(__half2*)&Ah[c].x;
            __half2 av1 = *(__half2*)&Ah[c].y;
            __half2 f0 = __hmax2(__hadd2(av0, *(__half2*)&rl.x), hz); // row r,   k 2q/2q+1
            __half2 f1 = __hmax2(__hadd2(av0, *(__half2*)&rh.x), hz); // row r+8
            __half2 f2 = __hmax2(__hadd2(av1, *(__half2*)&rl.y), hz); // row r,   k 2q+8/2q+9
            __half2 f3 = __hmax2(__hadd2(av1, *(__half2*)&rh.y), hz); // row r+8
            uint32_t a0 = *(uint32_t*)&f0, a1 = *(uint32_t*)&f1;
            uint32_t a2 = *(uint32_t*)&f2, a3 = *(uint32_t*)&f3;

            #pragma unroll
            for (int nbk = 0; nbk < 4; nbk++) {
                asm volatile(
                    "mma.sync.aligned.m16n8k16.row.col.f32.f16.f16.f32 "
                    "{%0,%1,%2,%3}, {%4,%5,%6,%7}, {%8,%9}, {%0,%1,%2,%3};"
                    : "+f"(acc[nbk][0]), "+f"(acc[nbk][1]),
                      "+f"(acc[nbk][2]), "+f"(acc[nbk][3])
                    : "r"(a0), "r"(a1), "r"(a2), "r"(a3),
                      "r"(wb[nbk][c][0]), "r"(wb[nbk][c][1]));
            }
        }

        // ---- epilogue: relu + w3 dot, butterfly over q, store ----
        float s0 = 0.f, s1 = 0.f;
        #pragma unroll
        for (int nbk = 0; nbk < 4; nbk++) {
            s0 = fmaf(fmaxf(acc[nbk][0], 0.f), w3v[nbk][0], s0);
            s0 = fmaf(fmaxf(acc[nbk][1], 0.f), w3v[nbk][1], s0);
            s1 = fmaf(fmaxf(acc[nbk][2], 0.f), w3v[nbk][0], s1);
            s1 = fmaf(fmaxf(acc[nbk][3], 0.f), w3v[nbk][1], s1);
        }
        s0 += __shfl_xor_sync(0xffffffffu, s0, 1);
        s0 += __shfl_xor_sync(0xffffffffu, s0, 2);
        s1 += __shfl_xor_sync(0xffffffffu, s1, 1);
        s1 += __shfl_xor_sync(0xffffffffu, s1, 2);
        if (q == 0) {
            outrow[j0 + r]     = s0 + b3;
            outrow[j0 + 8 + r] = s1 + b3;
        }
    }
}

// -------------------------------------------------------------------------
extern "C" void kernel_launch(void* const* d_in, const int* in_sizes, int n_in,
                              void* d_out, int out_size) {
    const float* h   = (const float*)d_in[0];
    const int*   pp  = (const int*)  d_in[1];
    const int*   pd  = (const int*)  d_in[2];
    const int*   rec = (const int*)  d_in[3];
    const float* Wq1 = (const float*)d_in[4];
    const float* Wk1 = (const float*)d_in[5];
    const float* Wq2 = (const float*)d_in[6];
    const float* Wk2 = (const float*)d_in[7];
    const float* W2  = (const float*)d_in[10];

    cudaMemcpyToSymbolAsync(cFC1W, d_in[8],  16 * 32 * sizeof(float), 0, cudaMemcpyDeviceToDevice, 0);
    cudaMemcpyToSymbolAsync(cFC1B, d_in[9],  32 * sizeof(float),      0, cudaMemcpyDeviceToDevice, 0);
    cudaMemcpyToSymbolAsync(cB2,   d_in[11], 32 * sizeof(float),      0, cudaMemcpyDeviceToDevice, 0);
    cudaMemcpyToSymbolAsync(cW3,   d_in[12], 32 * sizeof(float),      0, cudaMemcpyDeviceToDevice, 0);
    cudaMemcpyToSymbolAsync(cB3,   d_in[13], 1 * sizeof(float),       0, cudaMemcpyDeviceToDevice, 0);

    const int smem_bytes = Gn * BV_STRIDE * sizeof(uint32_t);   // 40960
    static int smem_set = 0;
    if (!smem_set) {
        cudaFuncSetAttribute(mlp_mma, cudaFuncAttributeMaxDynamicSharedMemorySize, smem_bytes);
        smem_set = 1;
    }

    prep1<<<Bn, 512>>>(h, pp, pd, Wq1, Wk1, Wq2, Wk2);
    prep2<<<dim3(4, Bn), 128>>>(h, rec);
    mlp_mma<<<dim3(Gn / 8, Bn), 256, smem_bytes>>>(W2, (float*)d_out);
}

// round 8
// speedup vs baseline: 1.1037x; 1.1037x over previous
#include <cuda_runtime.h>
#include <cuda_fp16.h>
#include <cstdint>

#define Bn 32
#define Gn 512
#define Dn 128
#define Hn 4
#define NORMF 0.17677669529663687f   // 1/sqrt(32)

// Scratch (device globals — no allocation allowed)
__device__ float g_M[4][Bn][Hn][Dn];        // [map: p1,p2,d1,d2][b][h][d]
__device__ uint32_t g_Ah2 [Bn * Gn * 16];   // fc1 i-side partial, half2, perm-k
__device__ uint32_t g_Bvh2[Bn * Gn * 16];   // fc1 j-side partial + b1, half2, perm-k

__constant__ float cFC1W[16][32];
__constant__ float cFC1B[32];
__constant__ float cB2[32];
__constant__ float cW3[32];
__constant__ float cB3[1];

// -------------------------------------------------------------------------
// prep1: grid (Hn, Bn). Block (hh, b): Q[hh] = q @ Wq[hh] (32 k), then
// M[map][b][hh][d] = NORM * sum_k Q·Wk[hh,d,k].
// -------------------------------------------------------------------------
__global__ void __launch_bounds__(512) prep1(const float* __restrict__ h,
                      const int* __restrict__ pp,
                      const int* __restrict__ pd,
                      const float* __restrict__ Wq1,
                      const float* __restrict__ Wk1,
                      const float* __restrict__ Wq2,
                      const float* __restrict__ Wk2) {
    int hh = blockIdx.x;
    int b  = blockIdx.y;
    int t  = threadIdx.x;   // 0..511
    __shared__ float shp[Dn], shd[Dn];
    __shared__ float sQp[16][4][32];   // [d-segment][map][k]
    __shared__ float sQ[4][32];

    int ip = pp[b], id = pd[b];
    if (t < Dn)            shp[t]      = h[(b * Gn + ip) * Dn + t];
    else if (t < 2 * Dn)   shd[t - Dn] = h[(b * Gn + id) * Dn + (t - Dn)];
    __syncthreads();

    {   // phase A: 16 segments of 8 d each
        int k = t & 31, seg = t >> 5;
        float q_p1 = 0.f, q_p2 = 0.f, q_d1 = 0.f, q_d2 = 0.f;
        #pragma unroll
        for (int dd = 0; dd < 8; dd++) {
            int d = seg * 8 + dd;
            float w1 = Wq1[(hh * Dn + d) * 32 + k];
            float w2 = Wq2[(hh * Dn + d) * 32 + k];
            float xp = shp[d], xd = shd[d];
            q_p1 = fmaf(xp, w1, q_p1);
            q_p2 = fmaf(xp, w2, q_p2);
            q_d1 = fmaf(xd, w1, q_d1);
            q_d2 = fmaf(xd, w2, q_d2);
        }
        sQp[seg][0][k] = q_p1;
        sQp[seg][1][k] = q_p2;
        sQp[seg][2][k] = q_d1;
        sQp[seg][3][k] = q_d2;
    }
    __syncthreads();
    if (t < 128) {
        int m = t >> 5, k = t & 31;
        float s = 0.f;
        #pragma unroll
        for (int seg = 0; seg < 16; seg++) s += sQp[seg][m][k];
        sQ[m][k] = s;
    }
    __syncthreads();

    {   // phase B: one (d, map) per thread
        int d = t >> 2, m = t & 3;
        const float* wk = (m & 1) ? Wk2 : Wk1;   // maps 0,2 -> Wk1; 1,3 -> Wk2
        const float4* wr = (const float4*)&wk[(hh * Dn + d) * 32];
        float acc = 0.f;
        #pragma unroll
        for (int i4 = 0; i4 < 8; i4++) {
            float4 a = __ldg(wr + i4);
            int k0 = i4 * 4;
            acc = fmaf(sQ[m][k0 + 0], a.x, acc);
            acc = fmaf(sQ[m][k0 + 1], a.y, acc);
            acc = fmaf(sQ[m][k0 + 2], a.z, acc);
            acc = fmaf(sQ[m][k0 + 3], a.w, acc);
        }
        g_M[m][b][hh][d] = acc * NORMF;
    }
}

// -------------------------------------------------------------------------
// prep2: per (b,g): u/v compat vectors folded through fc1, emitted as
// packed half2 in fragment-permuted k order.
// -------------------------------------------------------------------------
__global__ void __launch_bounds__(128) prep2(const float* __restrict__ h,
                                             const int* __restrict__ rec) {
    int b = blockIdx.y;
    int g = blockIdx.x * 128 + threadIdx.x;
    int t = threadIdx.x;
    __shared__ float sM[4][Hn][Dn];

    for (int idx = t; idx < 4 * Hn * Dn; idx += 128) {
        int w = idx >> 9;
        int r = idx & 511;
        (&sM[0][0][0])[idx] = (&g_M[0][0][0][0])[(w * Bn + b) * (Hn * Dn) + r];
    }
    __syncthreads();

    int nb = rec[b * Gn + g];
    const float4* hrow = (const float4*)(h + (b * Gn + g) * Dn);
    const float4* nrow = (const float4*)(h + (b * Gn + nb) * Dn);

    float u[8], v[8];
    #pragma unroll
    for (int l = 0; l < 8; l++) { u[l] = 0.f; v[l] = 0.f; }

    #pragma unroll 4
    for (int d4 = 0; d4 < Dn / 4; d4++) {
        float4 xv = __ldg(hrow + d4);
        float4 yv = __ldg(nrow + d4);
        float xs[4] = {xv.x, xv.y, xv.z, xv.w};
        float ys[4] = {yv.x, yv.y, yv.z, yv.w};
        #pragma unroll
        for (int r = 0; r < 4; r++) {
            int d = d4 * 4 + r;
            #pragma unroll
            for (int hh = 0; hh < Hn; hh++) {
                u[hh]     = fmaf(xs[r], sM[0][hh][d], u[hh]);
                u[4 + hh] = fmaf(ys[r], sM[1][hh][d], u[4 + hh]);
                v[hh]     = fmaf(xs[r], sM[2][hh][d], v[hh]);
                v[4 + hh] = fmaf(ys[r], sM[3][hh][d], v[4 + hh]);
            }
        }
    }

    float au[32], bu[32];
    #pragma unroll
    for (int k = 0; k < 32; k++) {
        float a = 0.f;
        float bb = cFC1B[k];
        #pragma unroll
        for (int l = 0; l < 8; l++) {
            a  = fmaf(u[l], cFC1W[l][k], a);
            bb = fmaf(v[l], cFC1W[8 + l][k], bb);
        }
        au[k] = a;
        bu[k] = bb;
    }

    uint32_t pa[16], pb[16];
    #pragma unroll
    for (int m = 0; m < 16; m++) {
        int c = m >> 3, rem = m & 7, qq = rem >> 1, s = rem & 1;
        int k0 = 16 * c + 2 * qq + 8 * s;
        __half2 ha = __floats2half2_rn(au[k0], au[k0 + 1]);
        __half2 hb = __floats2half2_rn(bu[k0], bu[k0 + 1]);
        pa[m] = *(uint32_t*)&ha;
        pb[m] = *(uint32_t*)&hb;
    }
    uint4* dA = (uint4*)&g_Ah2 [(b * Gn + g) * 16];
    uint4* dB = (uint4*)&g_Bvh2[(b * Gn + g) * 16];
    #pragma unroll
    for (int c4 = 0; c4 < 4; c4++) {
        dA[c4] = make_uint4(pa[4*c4], pa[4*c4+1], pa[4*c4+2], pa[4*c4+3]);
        dB[c4] = make_uint4(pb[4*c4], pb[4*c4+1], pb[4*c4+2], pb[4*c4+3]);
    }
}

// -------------------------------------------------------------------------
// mlp_mma: fc2 via mma m16n8k16 fp16 (f32 acc, bias pre-init); fc3 via a
// second MMA pair (fc2 C-fragments repacked as A-fragments, w3 replicated
// across N-cols as B) — no shuffles, no scalar dot.
// -------------------------------------------------------------------------
#define BV_STRIDE 20   // uint32 per smem row (80B, 16B-aligned)

__global__ void __launch_bounds__(256, 3) mlp_mma(const float* __restrict__ W2,
                                                  float* __restrict__ out) {
    extern __shared__ uint32_t sBv2[];   // [512][BV_STRIDE]
    const int t = threadIdx.x;
    const int w = t >> 5;
    const int lane = t & 31;
    const int q = lane & 3;          // threadID_in_group
    const int r = lane >> 2;         // groupID
    const int b = blockIdx.y;
    const int i = blockIdx.x * 8 + w;

    // ---- stage Bvh[b] into smem ----
    {
        const uint4* src = (const uint4*)&g_Bvh2[b * Gn * 16];
        for (int idx = t; idx < Gn * 4; idx += 256) {
            int j = idx >> 2, c4 = idx & 3;
            uint4 v = __ldg(src + idx);
            *(uint4*)&sBv2[j * BV_STRIDE + c4 * 4] = v;
        }
    }

    // ---- loop-invariant per-thread data ----
    uint2 Ah[2];
    {
        const uint32_t* ar = &g_Ah2[(b * Gn + i) * 16];
        Ah[0] = *(const uint2*)&ar[2 * q];
        Ah[1] = *(const uint2*)&ar[8 + 2 * q];
    }
    // W2 B-fragments (fp16)
    uint32_t wb[4][2][2];
    #pragma unroll
    for (int nbk = 0; nbk < 4; nbk++)
        #pragma unroll
        for (int c = 0; c < 2; c++) {
            int n = 8 * nbk + r;
            __half2 w0 = __floats2half2_rn(__ldg(&W2[(16*c + 2*q)     * 32 + n]),
                                           __ldg(&W2[(16*c + 2*q + 1) * 32 + n]));
            __half2 w1 = __floats2half2_rn(__ldg(&W2[(16*c + 2*q + 8) * 32 + n]),
                                           __ldg(&W2[(16*c + 2*q + 9) * 32 + n]));
            wb[nbk][c][0] = *(uint32_t*)&w0;
            wb[nbk][c][1] = *(uint32_t*)&w1;
        }
    // fc3 B-fragments: w3 at k=16c+{2q,2q+1} (b0) and +8 (b1), same for all cols
    uint32_t wb3[2][2];
    #pragma unroll
    for (int c = 0; c < 2; c++) {
        __half2 w0 = __floats2half2_rn(cW3[16*c + 2*q],     cW3[16*c + 2*q + 1]);
        __half2 w1 = __floats2half2_rn(cW3[16*c + 2*q + 8], cW3[16*c + 2*q + 9]);
        wb3[c][0] = *(uint32_t*)&w0;
        wb3[c][1] = *(uint32_t*)&w1;
    }
    float b2v[4][2];
    #pragma unroll
    for (int nbk = 0; nbk < 4; nbk++) {
        b2v[nbk][0] = cB2[8 * nbk + 2 * q];
        b2v[nbk][1] = cB2[8 * nbk + 2 * q + 1];
    }
    const float b3 = cB3[0];
    const __half2 hz = __float2half2_rn(0.f);
    __syncthreads();

    float* outrow = out + ((size_t)(b * Gn + i)) * Gn;
    const uint32_t* bvlo = sBv2 + r * BV_STRIDE + 2 * q;        // row j0+r
    const uint32_t* bvhi = sBv2 + (r + 8) * BV_STRIDE + 2 * q;  // row j0+r+8

    for (int jt = 0; jt < 32; jt++) {
        const int j0 = jt * 16;
        const uint32_t* pl = bvlo + j0 * BV_STRIDE;
        const uint32_t* ph = bvhi + j0 * BV_STRIDE;

        // acc init = bias
        float acc[4][4];
        #pragma unroll
        for (int nbk = 0; nbk < 4; nbk++) {
            acc[nbk][0] = b2v[nbk][0]; acc[nbk][1] = b2v[nbk][1];
            acc[nbk][2] = b2v[nbk][0]; acc[nbk][3] = b2v[nbk][1];
        }

        #pragma unroll
        for (int c = 0; c < 2; c++) {
            uint2 rl = *(const uint2*)(pl + 8 * c);
            uint2 rh = *(const uint2*)(ph + 8 * c);
            __half2 av0 = *(__half2*)&Ah[c].x;
            __half2 av1 = *(__half2*)&Ah[c].y;
            __half2 f0 = __hmax2(__hadd2(av0, *(__half2*)&rl.x), hz);
            __half2 f1 = __hmax2(__hadd2(av0, *(__half2*)&rh.x), hz);
            __half2 f2 = __hmax2(__hadd2(av1, *(__half2*)&rl.y), hz);
            __half2 f3 = __hmax2(__hadd2(av1, *(__half2*)&rh.y), hz);
            uint32_t a0 = *(uint32_t*)&f0, a1 = *(uint32_t*)&f1;
            uint32_t a2 = *(uint32_t*)&f2, a3 = *(uint32_t*)&f3;

            #pragma unroll
            for (int nbk = 0; nbk < 4; nbk++) {
                asm volatile(
                    "mma.sync.aligned.m16n8k16.row.col.f32.f16.f16.f32 "
                    "{%0,%1,%2,%3}, {%4,%5,%6,%7}, {%8,%9}, {%0,%1,%2,%3};"
                    : "+f"(acc[nbk][0]), "+f"(acc[nbk][1]),
                      "+f"(acc[nbk][2]), "+f"(acc[nbk][3])
                    : "r"(a0), "r"(a1), "r"(a2), "r"(a3),
                      "r"(wb[nbk][c][0]), "r"(wb[nbk][c][1]));
            }
        }

        // ---- epilogue: relu-pack acc as A-fragments, fc3 via 2 HMMA ----
        float o0 = b3, o1 = 0.f, o2 = b3, o3 = 0.f;
        #pragma unroll
        for (int c = 0; c < 2; c++) {
            __half2 g0 = __hmax2(__floats2half2_rn(acc[2*c][0],   acc[2*c][1]),   hz);
            __half2 g1 = __hmax2(__floats2half2_rn(acc[2*c][2],   acc[2*c][3]),   hz);
            __half2 g2 = __hmax2(__floats2half2_rn(acc[2*c+1][0], acc[2*c+1][1]), hz);
            __half2 g3 = __hmax2(__floats2half2_rn(acc[2*c+1][2], acc[2*c+1][3]), hz);
            uint32_t a0 = *(uint32_t*)&g0, a1 = *(uint32_t*)&g1;
            uint32_t a2 = *(uint32_t*)&g2, a3 = *(uint32_t*)&g3;
            asm volatile(
                "mma.sync.aligned.m16n8k16.row.col.f32.f16.f16.f32 "
                "{%0,%1,%2,%3}, {%4,%5,%6,%7}, {%8,%9}, {%0,%1,%2,%3};"
                : "+f"(o0), "+f"(o1), "+f"(o2), "+f"(o3)
                : "r"(a0), "r"(a1), "r"(a2), "r"(a3),
                  "r"(wb3[c][0]), "r"(wb3[c][1]));
        }
        if (q == 0) {
            outrow[j0 + r]     = o0;
            outrow[j0 + 8 + r] = o2;
        }
    }
}

// -------------------------------------------------------------------------
extern "C" void kernel_launch(void* const* d_in, const int* in_sizes, int n_in,
                              void* d_out, int out_size) {
    const float* h   = (const float*)d_in[0];
    const int*   pp  = (const int*)  d_in[1];
    const int*   pd  = (const int*)  d_in[2];
    const int*   rec = (const int*)  d_in[3];
    const float* Wq1 = (const float*)d_in[4];
    const float* Wk1 = (const float*)d_in[5];
    const float* Wq2 = (const float*)d_in[6];
    const float* Wk2 = (const float*)d_in[7];
    const float* W2  = (const float*)d_in[10];

    cudaMemcpyToSymbolAsync(cFC1W, d_in[8],  16 * 32 * sizeof(float), 0, cudaMemcpyDeviceToDevice, 0);
    cudaMemcpyToSymbolAsync(cFC1B, d_in[9],  32 * sizeof(float),      0, cudaMemcpyDeviceToDevice, 0);
    cudaMemcpyToSymbolAsync(cB2,   d_in[11], 32 * sizeof(float),      0, cudaMemcpyDeviceToDevice, 0);
    cudaMemcpyToSymbolAsync(cW3,   d_in[12], 32 * sizeof(float),      0, cudaMemcpyDeviceToDevice, 0);
    cudaMemcpyToSymbolAsync(cB3,   d_in[13], 1 * sizeof(float),       0, cudaMemcpyDeviceToDevice, 0);

    const int smem_bytes = Gn * BV_STRIDE * sizeof(uint32_t);   // 40960
    static int smem_set = 0;
    if (!smem_set) {
        cudaFuncSetAttribute(mlp_mma, cudaFuncAttributeMaxDynamicSharedMemorySize, smem_bytes);
        smem_set = 1;
    }

    prep1<<<dim3(Hn, Bn), 512>>>(h, pp, pd, Wq1, Wk1, Wq2, Wk2);
    prep2<<<dim3(4, Bn), 128>>>(h, rec);
    mlp_mma<<<dim3(Gn / 8, Bn), 256, smem_bytes>>>(W2, (float*)d_out);
}

// round 9
// speedup vs baseline: 1.1483x; 1.0404x over previous
#include <cuda_runtime.h>
#include <cuda_fp16.h>
#include <cstdint>

#define Bn 32
#define Gn 512
#define Dn 128
#define Hn 4
#define NORMF 0.17677669529663687f   // 1/sqrt(32)

// Scratch (device globals — no allocation allowed)
__device__ float g_M[4][Bn][Hn][Dn];        // [map: p1,p2,d1,d2][b][h][d]
__device__ uint32_t g_Ah2 [Bn * Gn * 16];   // fc1 i-side partial, half2, perm-k
__device__ uint32_t g_Bvh2[Bn * Gn * 16];   // fc1 j-side partial + b1, half2, perm-k

__constant__ float cFC1W[16][32];
__constant__ float cFC1B[32];
__constant__ float cB2[32];
__constant__ float cW3[32];
__constant__ float cB3[1];

// -------------------------------------------------------------------------
// prep1: grid (Hn, Bn). Block (hh, b): Q[hh] = q @ Wq[hh] (32 k), then
// M[map][b][hh][d] = NORM * sum_k Q·Wk[hh,d,k].
// -------------------------------------------------------------------------
__global__ void __launch_bounds__(512) prep1(const float* __restrict__ h,
                      const int* __restrict__ pp,
                      const int* __restrict__ pd,
                      const float* __restrict__ Wq1,
                      const float* __restrict__ Wk1,
                      const float* __restrict__ Wq2,
                      const float* __restrict__ Wk2) {
    int hh = blockIdx.x;
    int b  = blockIdx.y;
    int t  = threadIdx.x;   // 0..511
    __shared__ float shp[Dn], shd[Dn];
    __shared__ float sQp[16][4][32];   // [d-segment][map][k]
    __shared__ float sQ[4][32];

    int ip = pp[b], id = pd[b];
    if (t < Dn)            shp[t]      = h[(b * Gn + ip) * Dn + t];
    else if (t < 2 * Dn)   shd[t - Dn] = h[(b * Gn + id) * Dn + (t - Dn)];
    __syncthreads();

    {   // phase A: 16 segments of 8 d each
        int k = t & 31, seg = t >> 5;
        float q_p1 = 0.f, q_p2 = 0.f, q_d1 = 0.f, q_d2 = 0.f;
        #pragma unroll
        for (int dd = 0; dd < 8; dd++) {
            int d = seg * 8 + dd;
            float w1 = Wq1[(hh * Dn + d) * 32 + k];
            float w2 = Wq2[(hh * Dn + d) * 32 + k];
            float xp = shp[d], xd = shd[d];
            q_p1 = fmaf(xp, w1, q_p1);
            q_p2 = fmaf(xp, w2, q_p2);
            q_d1 = fmaf(xd, w1, q_d1);
            q_d2 = fmaf(xd, w2, q_d2);
        }
        sQp[seg][0][k] = q_p1;
        sQp[seg][1][k] = q_p2;
        sQp[seg][2][k] = q_d1;
        sQp[seg][3][k] = q_d2;
    }
    __syncthreads();
    if (t < 128) {
        int m = t >> 5, k = t & 31;
        float s = 0.f;
        #pragma unroll
        for (int seg = 0; seg < 16; seg++) s += sQp[seg][m][k];
        sQ[m][k] = s;
    }
    __syncthreads();

    {   // phase B: one (d, map) per thread
        int d = t >> 2, m = t & 3;
        const float* wk = (m & 1) ? Wk2 : Wk1;   // maps 0,2 -> Wk1; 1,3 -> Wk2
        const float4* wr = (const float4*)&wk[(hh * Dn + d) * 32];
        float acc = 0.f;
        #pragma unroll
        for (int i4 = 0; i4 < 8; i4++) {
            float4 a = __ldg(wr + i4);
            int k0 = i4 * 4;
            acc = fmaf(sQ[m][k0 + 0], a.x, acc);
            acc = fmaf(sQ[m][k0 + 1], a.y, acc);
            acc = fmaf(sQ[m][k0 + 2], a.z, acc);
            acc = fmaf(sQ[m][k0 + 3], a.w, acc);
        }
        g_M[m][b][hh][d] = acc * NORMF;
    }
}

// -------------------------------------------------------------------------
// prep2: 256 threads, 128 g per block; each g has 2 threads splitting the
// d-reduction, then half0 folds the A side and half1 folds the Bv side.
// Output: packed half2 in fragment-permuted k order.
// -------------------------------------------------------------------------
__global__ void __launch_bounds__(256) prep2(const float* __restrict__ h,
                                             const int* __restrict__ rec) {
    int b  = blockIdx.y;
    int t  = threadIdx.x;
    int gl = t & 127;          // g-lane
    int half = t >> 7;         // 0 or 1
    int g  = blockIdx.x * 128 + gl;

    __shared__ float sM[4][Hn][Dn];       // 8KB
    __shared__ float sX[128][8];          // partner's u (from half1)
    __shared__ float sY[128][8];          // half0's v  (to half1)

    for (int idx = t; idx < 4 * Hn * Dn; idx += 256) {
        int w = idx >> 9;
        int r = idx & 511;
        (&sM[0][0][0])[idx] = (&g_M[0][0][0][0])[(w * Bn + b) * (Hn * Dn) + r];
    }
    __syncthreads();

    int nb = rec[b * Gn + g];
    const float4* hrow = (const float4*)(h + (b * Gn + g) * Dn)  + half * 16;
    const float4* nrow = (const float4*)(h + (b * Gn + nb) * Dn) + half * 16;

    float u[8], v[8];
    #pragma unroll
    for (int l = 0; l < 8; l++) { u[l] = 0.f; v[l] = 0.f; }

    #pragma unroll 4
    for (int d4 = 0; d4 < 16; d4++) {
        float4 xv = __ldg(hrow + d4);
        float4 yv = __ldg(nrow + d4);
        float xs[4] = {xv.x, xv.y, xv.z, xv.w};
        float ys[4] = {yv.x, yv.y, yv.z, yv.w};
        #pragma unroll
        for (int r = 0; r < 4; r++) {
            int d = half * 64 + d4 * 4 + r;
            #pragma unroll
            for (int hh = 0; hh < Hn; hh++) {
                u[hh]     = fmaf(xs[r], sM[0][hh][d], u[hh]);
                u[4 + hh] = fmaf(ys[r], sM[1][hh][d], u[4 + hh]);
                v[hh]     = fmaf(xs[r], sM[2][hh][d], v[hh]);
                v[4 + hh] = fmaf(ys[r], sM[3][hh][d], v[4 + hh]);
            }
        }
    }
    // exchange: half1 gives u-partials to half0; half0 gives v-partials to half1
    if (half == 1) {
        #pragma unroll
        for (int l = 0; l < 8; l++) sX[gl][l] = u[l];
    } else {
        #pragma unroll
        for (int l = 0; l < 8; l++) sY[gl][l] = v[l];
    }
    __syncthreads();

    float z[8];
    if (half == 0) {
        #pragma unroll
        for (int l = 0; l < 8; l++) z[l] = u[l] + sX[gl][l];   // full u
    } else {
        #pragma unroll
        for (int l = 0; l < 8; l++) z[l] = sY[gl][l] + v[l];   // full v
    }

    // fold through fc1 half (A-side for half0, Bv-side for half1)
    float res[32];
    const float* Wslice = half ? &cFC1W[8][0] : &cFC1W[0][0];
    #pragma unroll
    for (int k = 0; k < 32; k++) {
        float a = half ? cFC1B[k] : 0.f;
        #pragma unroll
        for (int l = 0; l < 8; l++)
            a = fmaf(z[l], Wslice[l * 32 + k], a);
        res[k] = a;
    }

    uint32_t pk[16];
    #pragma unroll
    for (int m = 0; m < 16; m++) {
        int c = m >> 3, rem = m & 7, qq = rem >> 1, s = rem & 1;
        int k0 = 16 * c + 2 * qq + 8 * s;
        __half2 hp = __floats2half2_rn(res[k0], res[k0 + 1]);
        pk[m] = *(uint32_t*)&hp;
    }
    uint4* dst = half ? (uint4*)&g_Bvh2[(b * Gn + g) * 16]
                      : (uint4*)&g_Ah2 [(b * Gn + g) * 16];
    #pragma unroll
    for (int c4 = 0; c4 < 4; c4++)
        dst[c4] = make_uint4(pk[4*c4], pk[4*c4+1], pk[4*c4+2], pk[4*c4+3]);
}

// -------------------------------------------------------------------------
// mlp_mma: fc2 via mma m16n8k16 fp16 (f32 acc, bias pre-init); fc3 via MMA
// pair. TWO independent j-tiles per iteration for HMMA-level ILP.
// -------------------------------------------------------------------------
#define BV_STRIDE 20   // uint32 per smem row (80B, 16B-aligned)

__global__ void __launch_bounds__(256, 2) mlp_mma(const float* __restrict__ W2,
                                                  float* __restrict__ out) {
    extern __shared__ uint32_t sBv2[];   // [512][BV_STRIDE]
    const int t = threadIdx.x;
    const int w = t >> 5;
    const int lane = t & 31;
    const int q = lane & 3;          // threadID_in_group
    const int r = lane >> 2;         // groupID
    const int b = blockIdx.y;
    const int i = blockIdx.x * 8 + w;

    // ---- stage Bvh[b] into smem ----
    {
        const uint4* src = (const uint4*)&g_Bvh2[b * Gn * 16];
        for (int idx = t; idx < Gn * 4; idx += 256) {
            int j = idx >> 2, c4 = idx & 3;
            uint4 v = __ldg(src + idx);
            *(uint4*)&sBv2[j * BV_STRIDE + c4 * 4] = v;
        }
    }

    // ---- loop-invariant per-thread data ----
    uint2 Ah[2];
    {
        const uint32_t* ar = &g_Ah2[(b * Gn + i) * 16];
        Ah[0] = *(const uint2*)&ar[2 * q];
        Ah[1] = *(const uint2*)&ar[8 + 2 * q];
    }
    uint32_t wb[4][2][2];
    #pragma unroll
    for (int nbk = 0; nbk < 4; nbk++)
        #pragma unroll
        for (int c = 0; c < 2; c++) {
            int n = 8 * nbk + r;
            __half2 w0 = __floats2half2_rn(__ldg(&W2[(16*c + 2*q)     * 32 + n]),
                                           __ldg(&W2[(16*c + 2*q + 1) * 32 + n]));
            __half2 w1 = __floats2half2_rn(__ldg(&W2[(16*c + 2*q + 8) * 32 + n]),
                                           __ldg(&W2[(16*c + 2*q + 9) * 32 + n]));
            wb[nbk][c][0] = *(uint32_t*)&w0;
            wb[nbk][c][1] = *(uint32_t*)&w1;
        }
    uint32_t wb3[2][2];
    #pragma unroll
    for (int c = 0; c < 2; c++) {
        __half2 w0 = __floats2half2_rn(cW3[16*c + 2*q],     cW3[16*c + 2*q + 1]);
        __half2 w1 = __floats2half2_rn(cW3[16*c + 2*q + 8], cW3[16*c + 2*q + 9]);
        wb3[c][0] = *(uint32_t*)&w0;
        wb3[c][1] = *(uint32_t*)&w1;
    }
    float b2v[4][2];
    #pragma unroll
    for (int nbk = 0; nbk < 4; nbk++) {
        b2v[nbk][0] = cB2[8 * nbk + 2 * q];
        b2v[nbk][1] = cB2[8 * nbk + 2 * q + 1];
    }
    const float b3 = cB3[0];
    const __half2 hz = __float2half2_rn(0.f);
    __syncthreads();

    float* outrow = out + ((size_t)(b * Gn + i)) * Gn;
    const uint32_t* bvlo = sBv2 + r * BV_STRIDE + 2 * q;
    const uint32_t* bvhi = sBv2 + (r + 8) * BV_STRIDE + 2 * q;

    for (int jt = 0; jt < 16; jt++) {
        const int j0 = jt * 32;

        float acc[2][4][4];
        #pragma unroll
        for (int p = 0; p < 2; p++)
            #pragma unroll
            for (int nbk = 0; nbk < 4; nbk++) {
                acc[p][nbk][0] = b2v[nbk][0]; acc[p][nbk][1] = b2v[nbk][1];
                acc[p][nbk][2] = b2v[nbk][0]; acc[p][nbk][3] = b2v[nbk][1];
            }

        // two independent tiles p=0 (rows j0..j0+15) and p=1 (j0+16..j0+31)
        #pragma unroll
        for (int c = 0; c < 2; c++) {
            uint32_t a[2][4];
            #pragma unroll
            for (int p = 0; p < 2; p++) {
                const uint32_t* pl = bvlo + (j0 + 16 * p) * BV_STRIDE;
                const uint32_t* ph = bvhi + (j0 + 16 * p) * BV_STRIDE;
                uint2 rl = *(const uint2*)(pl + 8 * c);
                uint2 rh = *(const uint2*)(ph + 8 * c);
                __half2 av0 = *(__half2*)&Ah[c].x;
                __half2 av1 = *(__half2*)&Ah[c].y;
                __half2 f0 = __hmax2(__hadd2(av0, *(__half2*)&rl.x), hz);
                __half2 f1 = __hmax2(__hadd2(av0, *(__half2*)&rh.x), hz);
                __half2 f2 = __hmax2(__hadd2(av1, *(__half2*)&rl.y), hz);
                __half2 f3 = __hmax2(__hadd2(av1, *(__half2*)&rh.y), hz);
                a[p][0] = *(uint32_t*)&f0; a[p][1] = *(uint32_t*)&f1;
                a[p][2] = *(uint32_t*)&f2; a[p][3] = *(uint32_t*)&f3;
            }
            #pragma unroll
            for (int nbk = 0; nbk < 4; nbk++)
                #pragma unroll
                for (int p = 0; p < 2; p++) {
                    asm volatile(
                        "mma.sync.aligned.m16n8k16.row.col.f32.f16.f16.f32 "
                        "{%0,%1,%2,%3}, {%4,%5,%6,%7}, {%8,%9}, {%0,%1,%2,%3};"
                        : "+f"(acc[p][nbk][0]), "+f"(acc[p][nbk][1]),
                          "+f"(acc[p][nbk][2]), "+f"(acc[p][nbk][3])
                        : "r"(a[p][0]), "r"(a[p][1]), "r"(a[p][2]), "r"(a[p][3]),
                          "r"(wb[nbk][c][0]), "r"(wb[nbk][c][1]));
                }
        }

        // ---- epilogue: relu-pack, fc3 via 2 HMMA per tile ----
        float o[2][2];
        #pragma unroll
        for (int p = 0; p < 2; p++) {
            float o0 = b3, o1 = 0.f, o2 = b3, o3 = 0.f;
            #pragma unroll
            for (int c = 0; c < 2; c++) {
                __half2 g0 = __hmax2(__floats2half2_rn(acc[p][2*c][0],   acc[p][2*c][1]),   hz);
                __half2 g1 = __hmax2(__floats2half2_rn(acc[p][2*c][2],   acc[p][2*c][3]),   hz);
                __half2 g2 = __hmax2(__floats2half2_rn(acc[p][2*c+1][0], acc[p][2*c+1][1]), hz);
                __half2 g3 = __hmax2(__floats2half2_rn(acc[p][2*c+1][2], acc[p][2*c+1][3]), hz);
                uint32_t a0 = *(uint32_t*)&g0, a1 = *(uint32_t*)&g1;
                uint32_t a2 = *(uint32_t*)&g2, a3 = *(uint32_t*)&g3;
                asm volatile(
                    "mma.sync.aligned.m16n8k16.row.col.f32.f16.f16.f32 "
                    "{%0,%1,%2,%3}, {%4,%5,%6,%7}, {%8,%9}, {%0,%1,%2,%3};"
                    : "+f"(o0), "+f"(o1), "+f"(o2), "+f"(o3)
                    : "r"(a0), "r"(a1), "r"(a2), "r"(a3),
                      "r"(wb3[c][0]), "r"(wb3[c][1]));
            }
            o[p][0] = o0; o[p][1] = o2;
        }
        if (q == 0) {
            outrow[j0 + r]          = o[0][0];
            outrow[j0 + 8 + r]      = o[0][1];
            outrow[j0 + 16 + r]     = o[1][0];
            outrow[j0 + 24 + r]     = o[1][1];
        }
    }
}

// -------------------------------------------------------------------------
extern "C" void kernel_launch(void* const* d_in, const int* in_sizes, int n_in,
                              void* d_out, int out_size) {
    const float* h   = (const float*)d_in[0];
    const int*   pp  = (const int*)  d_in[1];
    const int*   pd  = (const int*)  d_in[2];
    const int*   rec = (const int*)  d_in[3];
    const float* Wq1 = (const float*)d_in[4];
    const float* Wk1 = (const float*)d_in[5];
    const float* Wq2 = (const float*)d_in[6];
    const float* Wk2 = (const float*)d_in[7];
    const float* W2  = (const float*)d_in[10];

    cudaMemcpyToSymbolAsync(cFC1W, d_in[8],  16 * 32 * sizeof(float), 0, cudaMemcpyDeviceToDevice, 0);
    cudaMemcpyToSymbolAsync(cFC1B, d_in[9],  32 * sizeof(float),      0, cudaMemcpyDeviceToDevice, 0);
    cudaMemcpyToSymbolAsync(cB2,   d_in[11], 32 * sizeof(float),      0, cudaMemcpyDeviceToDevice, 0);
    cudaMemcpyToSymbolAsync(cW3,   d_in[12], 32 * sizeof(float),      0, cudaMemcpyDeviceToDevice, 0);
    cudaMemcpyToSymbolAsync(cB3,   d_in[13], 1 * sizeof(float),       0, cudaMemcpyDeviceToDevice, 0);

    const int smem_bytes = Gn * BV_STRIDE * sizeof(uint32_t);   // 40960
    static int smem_set = 0;
    if (!smem_set) {
        cudaFuncSetAttribute(mlp_mma, cudaFuncAttributeMaxDynamicSharedMemorySize, smem_bytes);
        smem_set = 1;
    }

    prep1<<<dim3(Hn, Bn), 512>>>(h, pp, pd, Wq1, Wk1, Wq2, Wk2);
    prep2<<<dim3(4, Bn), 256>>>(h, rec);
    mlp_mma<<<dim3(Gn / 8, Bn), 256, smem_bytes>>>(W2, (float*)d_out);
}